// round 17
// baseline (speedup 1.0000x reference)
#include <cuda_runtime.h>
#include <cuda_bf16.h>
#include <math.h>

#define NCOMP 32
#define NLAT  64
#define MAXC  512
#define MAXG  4000
#define MAXCUT 1048576
#define NTILE 4000   // (n_genes/4) * (n_cells/128) for 4000x512
#define SORT_BLOCKS 64

#define L2E  1.4426950408889634f
#define SQC  0.8493218002880190f   // sqrt(L2E/2)

// Scratch (static device arrays — no runtime allocation)
static __device__ float  g_counts[MAXC * MAXG];                  // 8.2 MB
static __device__ float  g_loc[MAXG * NCOMP];                    // sigmoid(loc_w)
static __device__ float  g_isc[MAXG * NCOMP];                    // (1/scale)*SQC
static __device__ float  g_twv[MAXG * NCOMP];                    // (-log(scale)-0.5*log(2pi))*L2E
static __device__ __nv_bfloat16 g_l0b[MAXG * NCOMP];             // gathered logit_w * L2E, bf16
static __device__ float  g_grw[MAXG * NLAT];                     // gathered rho_weight
static __device__ float  g_latT[NLAT * MAXC];                    // latent transposed [l][cell]
static __device__ __nv_bfloat16 g_latb[MAXC * NLAT];             // latent bf16 [cell][l]
static __device__ __nv_bfloat16 g_lwb[(size_t)MAXG * NCOMP * NLAT]; // weights bf16 [g][c][k] (K-major)
static __device__ float  g_logrb[MAXG];
static __device__ float  g_rb[MAXG];
static __device__ float  g_lib[MAXC];
static __device__ float  g_loglib[MAXC];
static __device__ int    g_hist[NTILE];                          // cuts per gemm tile (total)
static __device__ int    g_tbase[NTILE];                         // tile start (stable)
static __device__ int    g_bh[NTILE * SORT_BLOCKS];              // per-tile per-block counts -> bases
static __device__ uint2  g_scut2[MAXCUT];                        // tile-sorted: {pair, gene<<16|coord16}
static __device__ int    g_done[2];                              // last-block tickets
static __device__ double g_acc;

__device__ __forceinline__ float ex2f(float x) {
    float r;
    asm("ex2.approx.ftz.f32 %0, %1;" : "=f"(r) : "f"(x));
    return r;
}

// ---------------- fragment-count scatter ----------------
__global__ void k_scatter(const int* __restrict__ ix, int n_frags) {
    int i = blockIdx.x * blockDim.x + threadIdx.x;
    int stride = gridDim.x * blockDim.x;
    for (int k = i; k < n_frags; k += stride) atomicAdd(&g_counts[ix[k]], 1.0f);
}

// ---------------- tile histogram + (last block) scan ----------------
__global__ void __launch_bounds__(256) k_histscan(const int* __restrict__ cpx, int n,
                                                  int n_genes, int ncb) {
    __shared__ int h[NTILE];
    __shared__ int wsum[8];
    __shared__ int lastflag;
    int tid = threadIdx.x;
    for (int i = tid; i < NTILE; i += 256) h[i] = 0;
    __syncthreads();
    int chunk = (n + SORT_BLOCKS - 1) / SORT_BLOCKS;
    int s = blockIdx.x * chunk;
    int e = min(s + chunk, n);
    for (int i = s + tid; i < e; i += 256) {
        unsigned pair = (unsigned)cpx[i];
        unsigned cell = pair / (unsigned)n_genes;
        unsigned gene = pair - cell * (unsigned)n_genes;
        int t = (int)((gene >> 2) * (unsigned)ncb + (cell >> 7));
        atomicAdd(&h[t], 1);
    }
    __syncthreads();
    // Save this block's counts: g_bh[t][blk]
    for (int i = tid; i < NTILE; i += 256)
        g_bh[i * SORT_BLOCKS + blockIdx.x] = h[i];
    __threadfence();
    if (tid == 0) lastflag = (atomicAdd(&g_done[0], 1) == SORT_BLOCKS - 1);
    __syncthreads();
    if (!lastflag) return;

    // Last block: per-tile cross-block exclusive scan (in place) + tile totals.
    for (int t = tid; t < NTILE; t += 256) {
        int run = 0;
        int* row = g_bh + t * SORT_BLOCKS;
#pragma unroll 8
        for (int b = 0; b < SORT_BLOCKS; b++) {
            int v = row[b];
            row[b] = run;
            run += v;
        }
        g_hist[t] = run;
    }
    __syncthreads();
    // Exclusive scan of tile totals -> g_tbase. 256 threads x 16 bins.
    int lane = tid & 31, wid = tid >> 5;
    int tv[16], tsum = 0;
#pragma unroll
    for (int j = 0; j < 16; j++) {
        int b = tid * 16 + j;
        tv[j] = (b < NTILE) ? g_hist[b] : 0;
        tsum += tv[j];
    }
    int inc = tsum;
#pragma unroll
    for (int o = 1; o < 32; o <<= 1) {
        int x = __shfl_up_sync(0xffffffffu, inc, o);
        if (lane >= o) inc += x;
    }
    if (lane == 31) wsum[wid] = inc;
    __syncthreads();
    if (wid == 0) {
        int w = (lane < 8) ? wsum[lane] : 0;
        int wi = w;
#pragma unroll
        for (int o = 1; o < 8; o <<= 1) {
            int x = __shfl_up_sync(0xffffffffu, wi, o);
            if (lane >= o) wi += x;
        }
        if (lane < 8) wsum[lane] = wi - w;
    }
    __syncthreads();
    int base = wsum[wid] + inc - tsum;
#pragma unroll
    for (int j = 0; j < 16; j++) {
        int b = tid * 16 + j;
        if (b < NTILE) g_tbase[b] = base;
        base += tv[j];
    }
}

// ---------------- placement (single pass; cursors from saved per-block bases) ----------------
__global__ void __launch_bounds__(256) k_ssort3(const int* __restrict__ cpx,
                                                const int* __restrict__ cgx,
                                                const float* __restrict__ coord,
                                                int n, int n_genes, int ncb) {
    __shared__ int cur[NTILE];
    int tid = threadIdx.x;
    for (int i = tid; i < NTILE; i += 256)
        cur[i] = g_tbase[i] + g_bh[i * SORT_BLOCKS + blockIdx.x];
    __syncthreads();
    int chunk = (n + SORT_BLOCKS - 1) / SORT_BLOCKS;
    int s = blockIdx.x * chunk;
    int e = min(s + chunk, n);
    for (int i = s + tid; i < e; i += 256) {
        unsigned pair = (unsigned)cpx[i];
        unsigned cell = pair / (unsigned)n_genes;
        unsigned gene = pair - cell * (unsigned)n_genes;
        int t = (int)((gene >> 2) * (unsigned)ncb + (cell >> 7));
        unsigned c16 = (unsigned)(coord[i] * 65535.0f + 0.5f);
        if (c16 > 65535u) c16 = 65535u;
        int pos = atomicAdd(&cur[t], 1);
        g_scut2[pos] = make_uint2(pair, ((unsigned)cgx[i] << 16) | c16);
    }
}

// ---------------- prep + weight transpose (fused; grid = n_genes blocks of 256) ----------------
__global__ void k_prep_tr(const float* __restrict__ loc_w, const float* __restrict__ scale_w,
                          const float* __restrict__ logit_w, const float* __restrict__ rho_weight,
                          const float* __restrict__ rho_bias, const float* __restrict__ libsize,
                          const float* __restrict__ latent, const float* __restrict__ logit_weight,
                          const int* __restrict__ genes_oi, const int* __restrict__ cells_oi,
                          int n_genes, int n_cells) {
    __shared__ float ts[NLAT][NCOMP + 1];
    int g = blockIdx.x;
    int tg = genes_oi[g];
    const float4* src = (const float4*)(logit_weight + (size_t)tg * (NLAT * NCOMP));
    int tid = threadIdx.x;
#pragma unroll
    for (int it = 0; it < 2; it++) {
        int i = it * 256 + tid;
        float4 v = src[i];
        int k = i >> 3, c4 = (i & 7) * 4;
        ts[k][c4] = v.x; ts[k][c4 + 1] = v.y; ts[k][c4 + 2] = v.z; ts[k][c4 + 3] = v.w;
    }
    __syncthreads();
    __nv_bfloat162* dst = (__nv_bfloat162*)(g_lwb + (size_t)g * (NCOMP * NLAT));
#pragma unroll
    for (int it = 0; it < 4; it++) {
        int i = it * 256 + tid;
        int c = i >> 5, k2 = (i & 31) * 2;
        dst[i] = __floats2bfloat162_rn(ts[k2][c], ts[k2 + 1][c]);
    }

    int total = n_genes * NCOMP + n_genes * NLAT + n_genes + n_cells * NLAT + n_cells;
    int stride = gridDim.x * 256;
    for (int i = blockIdx.x * 256 + tid; i < total; i += stride) {
        int r = i;
        if (r < n_genes * NCOMP) {
            int gg = r / NCOMP, c = r % NCOMP;
            int tgg = genes_oi[gg];
            float lw = loc_w[(size_t)tgg * NCOMP + c];
            float sw = scale_w[(size_t)tgg * NCOMP + c];
            float lg = logit_w[(size_t)tgg * NCOMP + c];
            float scale = 1e-5f + expf(sw);
            g_loc[r] = 1.0f / (1.0f + expf(-lw));
            g_isc[r] = (1.0f / scale) * SQC;
            g_twv[r] = (-logf(scale) - 0.91893853320467274f) * L2E;
            g_l0b[r] = __float2bfloat16(lg * L2E);
            continue;
        }
        r -= n_genes * NCOMP;
        if (r < n_genes * NLAT) {
            int gg = r / NLAT, l = r % NLAT;
            g_grw[r] = rho_weight[(size_t)genes_oi[gg] * NLAT + l];
            continue;
        }
        r -= n_genes * NLAT;
        if (r < n_genes) {
            float rb = rho_bias[genes_oi[r]];
            g_rb[r] = rb;
            g_logrb[r] = logf(rb);
            continue;
        }
        r -= n_genes;
        if (r < n_cells * NLAT) {
            int l = r / n_cells, cell = r % n_cells;
            float v = latent[(size_t)cell * NLAT + l];
            g_latT[r] = v;
            g_latb[(size_t)cell * NLAT + l] = __float2bfloat16(v);
            continue;
        }
        r -= n_cells * NLAT;
        {
            float lb = libsize[cells_oi[r]];
            g_lib[r] = lb;
            g_loglib[r] = logf(lb);
        }
    }
}

// ---------------- fused GEMM + mixture likelihood ----------------
// CTA = tile (4 genes x 128 cells). MMA computes delta*log2(e) into smem bf16;
// the cut loop consumes it directly with ex2-only exponentials.
#define ASTRIDE 72   // padded A/B row stride (bf16)
#define CSTRIDE 136  // padded C stage row stride (bf16)
#define SM_BYTES 36864

__device__ __forceinline__ void mma_bf16(float* c, const unsigned* a, const unsigned* b) {
    asm volatile(
        "mma.sync.aligned.m16n8k16.row.col.f32.bf16.bf16.f32 "
        "{%0,%1,%2,%3}, {%4,%5,%6,%7}, {%8,%9}, {%0,%1,%2,%3};"
        : "+f"(c[0]), "+f"(c[1]), "+f"(c[2]), "+f"(c[3])
        : "r"(a[0]), "r"(a[1]), "r"(a[2]), "r"(a[3]), "r"(b[0]), "r"(b[1]));
}

__global__ void __launch_bounds__(256) k_gemm_mix(int n_cells, int n_genes) {
    __shared__ __align__(16) char smraw[SM_BYTES];
    __shared__ float red[8];
    __nv_bfloat16* As = (__nv_bfloat16*)smraw;
    __nv_bfloat16* Bs = As + 128 * ASTRIDE;
    __nv_bfloat16* Cs = (__nv_bfloat16*)smraw;          // reused after MMA

    int tid = threadIdx.x;
    int gbase = blockIdx.x * 4;     // 4 genes -> 128 delta cols
    int cbase = blockIdx.y * 128;   // 128 cells
    int ncb = n_cells >> 7;
    int tile = blockIdx.x * ncb + blockIdx.y;

    const uint4* asrc = (const uint4*)(g_latb + (size_t)cbase * NLAT);
    const uint4* bsrc = (const uint4*)(g_lwb + (size_t)gbase * (NCOMP * NLAT));
#pragma unroll
    for (int i = 0; i < 4; i++) {
        int cid = i * 256 + tid;
        int row = cid >> 3, ch = cid & 7;
        *(uint4*)(As + row * ASTRIDE + ch * 8) = asrc[cid];
        *(uint4*)(Bs + row * ASTRIDE + ch * 8) = bsrc[cid];
    }
    __syncthreads();

    int wid = tid >> 5, lane = tid & 31;
    int wm = (wid & 3) * 32;
    int wn = (wid >> 2) * 64;
    int g = lane >> 2, t = lane & 3;

    float acc[2][8][4];
#pragma unroll
    for (int mt = 0; mt < 2; mt++)
#pragma unroll
        for (int nt = 0; nt < 8; nt++)
#pragma unroll
            for (int j = 0; j < 4; j++) acc[mt][nt][j] = 0.0f;

#pragma unroll
    for (int kc = 0; kc < 4; kc++) {
        int k0 = kc * 16;
        unsigned a[2][4];
#pragma unroll
        for (int mt = 0; mt < 2; mt++) {
            int r0 = wm + mt * 16 + g;
            a[mt][0] = *(const unsigned*)(As + (r0)     * ASTRIDE + k0 + 2 * t);
            a[mt][1] = *(const unsigned*)(As + (r0 + 8) * ASTRIDE + k0 + 2 * t);
            a[mt][2] = *(const unsigned*)(As + (r0)     * ASTRIDE + k0 + 2 * t + 8);
            a[mt][3] = *(const unsigned*)(As + (r0 + 8) * ASTRIDE + k0 + 2 * t + 8);
        }
        unsigned b[8][2];
#pragma unroll
        for (int nt = 0; nt < 8; nt++) {
            int n0 = wn + nt * 8 + g;
            b[nt][0] = *(const unsigned*)(Bs + n0 * ASTRIDE + k0 + 2 * t);
            b[nt][1] = *(const unsigned*)(Bs + n0 * ASTRIDE + k0 + 2 * t + 8);
        }
#pragma unroll
        for (int mt = 0; mt < 2; mt++)
#pragma unroll
            for (int nt = 0; nt < 8; nt++)
                mma_bf16(acc[mt][nt], a[mt], b[nt]);
    }
    __syncthreads();  // As/Bs dead; stage Cs

    // Stage delta * log2(e) (bf16) into Cs.
#pragma unroll
    for (int nt = 0; nt < 8; nt++) {
        int col = wn + nt * 8 + 2 * t;
#pragma unroll
        for (int mt = 0; mt < 2; mt++) {
            int r0 = wm + mt * 16 + g;
            *(__nv_bfloat162*)(Cs + r0 * CSTRIDE + col) =
                __floats2bfloat162_rn(acc[mt][nt][0] * L2E, acc[mt][nt][1] * L2E);
            *(__nv_bfloat162*)(Cs + (r0 + 8) * CSTRIDE + col) =
                __floats2bfloat162_rn(acc[mt][nt][2] * L2E, acc[mt][nt][3] * L2E);
        }
    }
    __syncthreads();

    // Cut loop: teams of 4 lanes per cut, 8 comps per lane. Warp-uniform trip count.
    int start = g_tbase[tile];
    int end = start + g_hist[tile];
    int sub = lane >> 2;     // team id within warp (8 cuts/warp)
    int q = lane & 3;        // comp quarter
    float local = 0.0f;
    for (int kb = start + wid * 8; kb < end; kb += 64) {
        int k = kb + sub;
        bool valid = k < end;
        uint2 rec = g_scut2[valid ? k : start];
        unsigned pair = rec.x;
        int gene = (int)(rec.y >> 16);                       // cgx gene (independent)
        float x = (float)(rec.y & 0xFFFFu) * (1.0f / 65535.0f);
        unsigned cell = pair / (unsigned)n_genes;
        int gi = (int)(pair - cell * (unsigned)n_genes) - gbase;
        int row = (int)cell - cbase;

        // 8 delta comps (log2-scaled) from smem, 8 table comps from global (L2-hot).
        uint4 dv = *(const uint4*)(Cs + row * CSTRIDE + gi * 32 + q * 8);
        uint4 lv = *(const uint4*)(g_l0b + gene * NCOMP + q * 8);
        const __nv_bfloat162* pd = (const __nv_bfloat162*)&dv;
        const __nv_bfloat162* pl = (const __nv_bfloat162*)&lv;
        int tb = gene * NCOMP + q * 8;
        float4 L0 = *(const float4*)(g_loc + tb);
        float4 L1 = *(const float4*)(g_loc + tb + 4);
        float4 S0 = *(const float4*)(g_isc + tb);
        float4 S1 = *(const float4*)(g_isc + tb + 4);
        float4 W0 = *(const float4*)(g_twv + tb);
        float4 W1 = *(const float4*)(g_twv + tb + 4);

        float lg[8];
#pragma unroll
        for (int j = 0; j < 4; j++) {
            float2 d = __bfloat1622float2(pd[j]);
            float2 l = __bfloat1622float2(pl[j]);
            lg[2 * j] = d.x + l.x;
            lg[2 * j + 1] = d.y + l.y;
        }
        float num = 0.0f, den = 0.0f, u;
        den += ex2f(lg[0]); u = (x - L0.x) * S0.x; num += ex2f(fmaf(-u, u, lg[0] + W0.x));
        den += ex2f(lg[1]); u = (x - L0.y) * S0.y; num += ex2f(fmaf(-u, u, lg[1] + W0.y));
        den += ex2f(lg[2]); u = (x - L0.z) * S0.z; num += ex2f(fmaf(-u, u, lg[2] + W0.z));
        den += ex2f(lg[3]); u = (x - L0.w) * S0.w; num += ex2f(fmaf(-u, u, lg[3] + W0.w));
        den += ex2f(lg[4]); u = (x - L1.x) * S1.x; num += ex2f(fmaf(-u, u, lg[4] + W1.x));
        den += ex2f(lg[5]); u = (x - L1.y) * S1.y; num += ex2f(fmaf(-u, u, lg[5] + W1.y));
        den += ex2f(lg[6]); u = (x - L1.z) * S1.z; num += ex2f(fmaf(-u, u, lg[6] + W1.z));
        den += ex2f(lg[7]); u = (x - L1.w) * S1.w; num += ex2f(fmaf(-u, u, lg[7] + W1.w));

        num += __shfl_xor_sync(0xffffffffu, num, 1);
        num += __shfl_xor_sync(0xffffffffu, num, 2);
        den += __shfl_xor_sync(0xffffffffu, den, 1);
        den += __shfl_xor_sync(0xffffffffu, den, 2);

        if (q == 0 && valid)
            local += __logf(fmaxf(num, 1e-37f)) - __logf(den);
    }

    // Block reduce -> double accumulator.
#pragma unroll
    for (int s = 16; s > 0; s >>= 1) local += __shfl_xor_sync(0xffffffffu, local, s);
    if (lane == 0) red[wid] = local;
    __syncthreads();
    if (tid == 0) {
        float s = 0.0f;
        for (int i = 0; i < 8; i++) s += red[i];
        atomicAdd(&g_acc, (double)s);
    }
}

// ---------------- Poisson fragment-count likelihood (+ final output in last block) ----------------
__global__ void k_poisson(int n_cells, int n_genes, float* out) {
    __shared__ float rw_s[8][NLAT];
    __shared__ float red[8];

    int gbase = blockIdx.x * 8;
    int cell = blockIdx.y * 256 + threadIdx.x;
    int tid = threadIdx.x;

    for (int i = tid; i < 8 * NLAT; i += 256) {
        int j = i / NLAT, l = i % NLAT;
        int g = gbase + j;
        rw_s[j][l] = (g < n_genes) ? g_grw[g * NLAT + l] : 0.0f;
    }
    __syncthreads();

    float lsum = 0.0f;
    if (cell < n_cells) {
        float acc[8] = {0, 0, 0, 0, 0, 0, 0, 0};
#pragma unroll 16
        for (int l = 0; l < NLAT; l++) {
            float lat = g_latT[l * n_cells + cell];
#pragma unroll
            for (int j = 0; j < 8; j++)
                acc[j] = fmaf(lat, rw_s[j][l], acc[j]);
        }
        float lib = g_lib[cell], ll = g_loglib[cell];
#pragma unroll
        for (int j = 0; j < 8; j++) {
            int g = gbase + j;
            if (g >= n_genes) continue;
            float rho = acc[j];
            float fe = g_rb[g] * __expf(rho) * lib;
            float cnt = g_counts[(size_t)cell * n_genes + g];
            float t = cnt * (g_logrb[g] + rho + ll) - fe;
            if (cnt > 1.5f) t -= lgammaf(cnt + 1.0f);
            lsum += t;
        }
    }
    for (int s = 16; s > 0; s >>= 1) lsum += __shfl_xor_sync(0xffffffffu, lsum, s);
    int wid = tid >> 5;
    if ((tid & 31) == 0) red[wid] = lsum;
    __syncthreads();
    if (tid == 0) {
        float s = 0.0f;
        for (int i = 0; i < 8; i++) s += red[i];
        atomicAdd(&g_acc, (double)s);
        __threadfence();
        int nblk = gridDim.x * gridDim.y;
        if (atomicAdd(&g_done[1], 1) == nblk - 1) {
            double v = atomicAdd(&g_acc, 0.0);   // read with device-scope visibility
            out[0] = (float)(-v);
        }
    }
}

extern "C" void kernel_launch(void* const* d_in, const int* in_sizes, int n_in,
                              void* d_out, int out_size) {
    const int*   frag_ix      = (const int*)d_in[0];
    const float* coord        = (const float*)d_in[1];
    const float* latent       = (const float*)d_in[2];
    const int*   genes_oi     = (const int*)d_in[3];
    const int*   cells_oi     = (const int*)d_in[4];
    const int*   cpx          = (const int*)d_in[5];
    const int*   cgx          = (const int*)d_in[6];
    const float* loc_w        = (const float*)d_in[9];
    const float* scale_w      = (const float*)d_in[10];
    const float* logit_w      = (const float*)d_in[11];
    const float* logit_weight = (const float*)d_in[12];
    const float* rho_weight   = (const float*)d_in[13];
    const float* rho_bias     = (const float*)d_in[14];
    const float* libsize      = (const float*)d_in[15];

    int n_frags = in_sizes[0];
    int n_cuts  = in_sizes[1];
    int n_genes = in_sizes[3];
    int n_cells = in_sizes[4];
    int ncb     = n_cells >> 7;

    void *p_counts, *p_acc, *p_done;
    cudaGetSymbolAddress(&p_counts, g_counts);
    cudaGetSymbolAddress(&p_acc, g_acc);
    cudaGetSymbolAddress(&p_done, g_done);
    cudaMemsetAsync(p_counts, 0, (size_t)n_cells * n_genes * sizeof(float));
    cudaMemsetAsync(p_acc, 0, sizeof(double));
    cudaMemsetAsync(p_done, 0, 2 * sizeof(int));

    k_scatter<<<592, 256>>>(frag_ix, n_frags);
    k_histscan<<<SORT_BLOCKS, 256>>>(cpx, n_cuts, n_genes, ncb);
    k_ssort3<<<SORT_BLOCKS, 256>>>(cpx, cgx, coord, n_cuts, n_genes, ncb);
    k_prep_tr<<<n_genes, 256>>>(loc_w, scale_w, logit_w, rho_weight, rho_bias, libsize,
                                latent, logit_weight, genes_oi, cells_oi, n_genes, n_cells);
    dim3 gg(n_genes / 4, ncb);
    k_gemm_mix<<<gg, 256>>>(n_cells, n_genes);
    dim3 gp((n_genes + 7) / 8, (n_cells + 255) / 256);
    k_poisson<<<gp, 256>>>(n_cells, n_genes, (float*)d_out);
}